// round 2
// baseline (speedup 1.0000x reference)
#include <cuda_runtime.h>
#include <cstddef>

// Problem constants
#define T_LEN 800
#define NB    32
#define LIN   4000
#define FEATC 320
#define KW    19
#define PADL  7
#define NSTATE 1024
#define NZ    5
#define CN    5120           // NSTATE * NZ
#define M_TOT (T_LEN * NB)   // 25600

// Scratch (no allocations allowed)
__device__ float g_y[M_TOT * FEATC];      // conv features, [M, 320]
__device__ float g_logz_over_T[NB];

// ---------------------------------------------------------------------------
// helpers
// ---------------------------------------------------------------------------
__device__ __forceinline__ float fast_tanh(float x) {
    float r;
    asm("tanh.approx.f32 %0, %1;" : "=f"(r) : "f"(x));
    return r;
}
__device__ __forceinline__ void fma2(unsigned long long& d,
                                     unsigned long long a,
                                     unsigned long long b) {
    asm("fma.rn.f32x2 %0, %1, %2, %0;" : "+l"(d) : "l"(a), "l"(b));
}
__device__ __forceinline__ unsigned long long pack2(float x) {
    unsigned long long r;
    asm("mov.b64 %0, {%1, %1};" : "=l"(r) : "f"(x));
    return r;
}
__device__ __forceinline__ float2 unpack2(unsigned long long v) {
    float2 f;
    asm("mov.b64 {%0, %1}, %2;" : "=f"(f.x), "=f"(f.y) : "l"(v));
    return f;
}

// ---------------------------------------------------------------------------
// Kernel 1: strided conv (SAME, pad 7) + tanh -> g_y[(t*NB+n)*FEATC + f]
// grid: (T/16, NB), block: 320 threads (one per output channel)
// ---------------------------------------------------------------------------
#define TCHUNK 16
#define XSEG ((TCHUNK - 1) * 5 + KW)   // 94

__global__ void conv_kernel(const float* __restrict__ x,
                            const float* __restrict__ w,
                            const float* __restrict__ b) {
    __shared__ float sw[FEATC * KW];
    __shared__ float sb[FEATC];
    __shared__ float sx[XSEG];

    const int n  = blockIdx.y;
    const int t0 = blockIdx.x * TCHUNK;
    const int tid = threadIdx.x;

    for (int i = tid; i < FEATC * KW; i += blockDim.x) sw[i] = w[i];
    if (tid < FEATC) sb[tid] = b[tid];
    const int base = t0 * 5 - PADL;
    for (int i = tid; i < XSEG; i += blockDim.x) {
        int gx = base + i;
        sx[i] = (gx >= 0 && gx < LIN) ? x[n * LIN + gx] : 0.0f;
    }
    __syncthreads();

    const int f = tid;
    float acc[TCHUNK];
#pragma unroll
    for (int i = 0; i < TCHUNK; i++) acc[i] = sb[f];
#pragma unroll
    for (int k = 0; k < KW; k++) {
        const float wk = sw[f * KW + k];
#pragma unroll
        for (int i = 0; i < TCHUNK; i++) acc[i] += wk * sx[i * 5 + k];
    }
#pragma unroll
    for (int i = 0; i < TCHUNK; i++) {
        const int row = (t0 + i) * NB + n;
        g_y[row * FEATC + f] = fast_tanh(acc[i]);
    }
}

// ---------------------------------------------------------------------------
// Kernel 2: GEMM  out[m, c] = 5*tanh(sum_f y[m,f]*W[f,c] + bias[c])
// 128x128 tile, 256 threads, 8x8 per thread, packed f32x2 FMAs.
// M=25600 (200 tiles), N=5120 (40 tiles), K=320 (20 tiles of 16). No bounds.
// ---------------------------------------------------------------------------
#define BM 128
#define BN 128
#define BK 16
#define APITCH 132

__global__ __launch_bounds__(256, 2)
void gemm_kernel(const float* __restrict__ lin_w,
                 const float* __restrict__ lin_b,
                 float* __restrict__ out) {
    __shared__ float As[2][BK][APITCH];
    __shared__ float Bs[2][BK][BN];

    const int bm = blockIdx.y, bn = blockIdx.x;
    const int tid = threadIdx.x;
    const int tx = tid & 15, ty = tid >> 4;

    const float* A = g_y + (size_t)bm * BM * FEATC;
    const float* B = lin_w + bn * BN;

    unsigned long long acc[8][4];
#pragma unroll
    for (int i = 0; i < 8; i++)
#pragma unroll
        for (int j = 0; j < 4; j++) acc[i][j] = 0ull;

    // tile loader
    const int a_row = tid >> 2;            // 0..63 (+64 on second pass)
    const int a_k4  = (tid & 3) * 4;
    const int b_k   = tid >> 5;            // 0..7 (+8 on second pass)
    const int b_n4  = (tid & 31) * 4;

#define LOAD_TILE(kt, buf)                                                      \
    do {                                                                        \
        _Pragma("unroll")                                                       \
        for (int it = 0; it < 2; it++) {                                        \
            int row = a_row + it * 64;                                          \
            float4 v = *(const float4*)(A + (size_t)row * FEATC + (kt) * BK + a_k4); \
            As[buf][a_k4 + 0][row] = v.x;                                       \
            As[buf][a_k4 + 1][row] = v.y;                                       \
            As[buf][a_k4 + 2][row] = v.z;                                       \
            As[buf][a_k4 + 3][row] = v.w;                                       \
        }                                                                       \
        _Pragma("unroll")                                                       \
        for (int it = 0; it < 2; it++) {                                        \
            int kk = b_k + it * 8;                                              \
            *(float4*)&Bs[buf][kk][b_n4] =                                      \
                *(const float4*)(B + (size_t)((kt) * BK + kk) * CN + b_n4);     \
        }                                                                       \
    } while (0)

    LOAD_TILE(0, 0);
    __syncthreads();

    const int nk = FEATC / BK;  // 20
    for (int kt = 0; kt < nk; kt++) {
        const int buf = kt & 1;
        if (kt + 1 < nk) LOAD_TILE(kt + 1, buf ^ 1);
#pragma unroll
        for (int k = 0; k < BK; k++) {
            float a[8];
            float4 a0 = *(const float4*)&As[buf][k][ty * 8];
            float4 a1 = *(const float4*)&As[buf][k][ty * 8 + 4];
            a[0] = a0.x; a[1] = a0.y; a[2] = a0.z; a[3] = a0.w;
            a[4] = a1.x; a[5] = a1.y; a[6] = a1.z; a[7] = a1.w;
            unsigned long long bv[4];
            const unsigned long long* bp =
                (const unsigned long long*)&Bs[buf][k][tx * 8];
            bv[0] = bp[0]; bv[1] = bp[1]; bv[2] = bp[2]; bv[3] = bp[3];
#pragma unroll
            for (int i = 0; i < 8; i++) {
                unsigned long long ap = pack2(a[i]);
#pragma unroll
                for (int j = 0; j < 4; j++) fma2(acc[i][j], ap, bv[j]);
            }
        }
        __syncthreads();
    }

    // epilogue: + bias, 5*tanh, store
    const int col0 = bn * BN + tx * 8;
    float4 bb0 = *(const float4*)(lin_b + col0);
    float4 bb1 = *(const float4*)(lin_b + col0 + 4);
    float bias[8] = {bb0.x, bb0.y, bb0.z, bb0.w, bb1.x, bb1.y, bb1.z, bb1.w};

#pragma unroll
    for (int i = 0; i < 8; i++) {
        const int row = bm * BM + ty * 8 + i;
        float o[8];
#pragma unroll
        for (int j = 0; j < 4; j++) {
            float2 p = unpack2(acc[i][j]);
            o[2 * j] = p.x;
            o[2 * j + 1] = p.y;
        }
#pragma unroll
        for (int jj = 0; jj < 8; jj++)
            o[jj] = 5.0f * fast_tanh(o[jj] + bias[jj]);
        float4* dst = (float4*)(out + (size_t)row * CN + col0);
        dst[0] = make_float4(o[0], o[1], o[2], o[3]);
        dst[1] = make_float4(o[4], o[5], o[6], o[7]);
    }
}

// ---------------------------------------------------------------------------
// Kernel 3: log-semiring forward scan. One block per batch element.
// alpha_new[c] = LSE_z( M[t,n,c,z] + alpha[pred(c,z)] )
// pred(c,0)=c ; pred(c,1+j)=j*256 + c/4
// ---------------------------------------------------------------------------
__global__ __launch_bounds__(1024, 1)
void scan_kernel(const float* __restrict__ scores) {
    __shared__ float alpha[2][NSTATE];
    __shared__ float rmax[32];
    __shared__ float rsum[32];
    __shared__ float sfinal;

    const int n = blockIdx.x;
    const int c = threadIdx.x;
    const int q = c >> 2;

    alpha[0][c] = 0.0f;
    __syncthreads();

    const float* p = scores + (size_t)n * CN + (size_t)c * NZ;
    const size_t tstride = (size_t)NB * CN;

    float m0 = p[0], m1 = p[1], m2 = p[2], m3 = p[3], m4 = p[4];
    int cur = 0;
    for (int t = 0; t < T_LEN; t++) {
        float n0 = 0.f, n1 = 0.f, n2 = 0.f, n3 = 0.f, n4 = 0.f;
        if (t + 1 < T_LEN) {
            const float* pn = p + (size_t)(t + 1) * tstride;
            n0 = pn[0]; n1 = pn[1]; n2 = pn[2]; n3 = pn[3]; n4 = pn[4];
        }
        const float s0 = m0 + alpha[cur][c];
        const float s1 = m1 + alpha[cur][q];
        const float s2 = m2 + alpha[cur][q + 256];
        const float s3 = m3 + alpha[cur][q + 512];
        const float s4 = m4 + alpha[cur][q + 768];
        float mx = fmaxf(fmaxf(fmaxf(s0, s1), fmaxf(s2, s3)), s4);
        float sum = __expf(s0 - mx) + __expf(s1 - mx) + __expf(s2 - mx) +
                    __expf(s3 - mx) + __expf(s4 - mx);
        alpha[cur ^ 1][c] = mx + __logf(sum);
        __syncthreads();
        cur ^= 1;
        m0 = n0; m1 = n1; m2 = n2; m3 = n3; m4 = n4;
    }

    // final logsumexp over the 1024 states
    const float v = alpha[cur][c];
    float mx = v;
#pragma unroll
    for (int o = 16; o > 0; o >>= 1)
        mx = fmaxf(mx, __shfl_xor_sync(0xffffffffu, mx, o));
    if ((c & 31) == 0) rmax[c >> 5] = mx;
    __syncthreads();
    if (c < 32) {
        float m2r = rmax[c];
#pragma unroll
        for (int o = 16; o > 0; o >>= 1)
            m2r = fmaxf(m2r, __shfl_xor_sync(0xffffffffu, m2r, o));
        if (c == 0) sfinal = m2r;
    }
    __syncthreads();
    float e = __expf(v - sfinal);
#pragma unroll
    for (int o = 16; o > 0; o >>= 1)
        e += __shfl_xor_sync(0xffffffffu, e, o);
    if ((c & 31) == 0) rsum[c >> 5] = e;
    __syncthreads();
    if (c < 32) {
        float s = rsum[c];
#pragma unroll
        for (int o = 16; o > 0; o >>= 1)
            s += __shfl_xor_sync(0xffffffffu, s, o);
        if (c == 0)
            g_logz_over_T[n] = (sfinal + logf(s)) * (1.0f / (float)T_LEN);
    }
}

// ---------------------------------------------------------------------------
// Kernel 4: in-place global-norm subtraction. One block per (t,n) row.
// ---------------------------------------------------------------------------
__global__ void sub_kernel(float* __restrict__ out) {
    const int row = blockIdx.x;             // t*NB + n
    const float s = g_logz_over_T[row & (NB - 1)];
    float4* p = (float4*)(out + (size_t)row * CN);
#pragma unroll
    for (int j = threadIdx.x; j < CN / 4; j += 256) {
        float4 v = p[j];
        v.x -= s; v.y -= s; v.z -= s; v.w -= s;
        p[j] = v;
    }
}

// ---------------------------------------------------------------------------
extern "C" void kernel_launch(void* const* d_in, const int* in_sizes, int n_in,
                              void* d_out, int out_size) {
    const float* x      = (const float*)d_in[0];
    const float* conv_w = (const float*)d_in[1];
    const float* conv_b = (const float*)d_in[2];
    const float* lin_w  = (const float*)d_in[3];
    const float* lin_b  = (const float*)d_in[4];
    float* out = (float*)d_out;

    conv_kernel<<<dim3(T_LEN / TCHUNK, NB), FEATC>>>(x, conv_w, conv_b);
    gemm_kernel<<<dim3(CN / BN, M_TOT / BM), 256>>>(lin_w, lin_b, out);
    scan_kernel<<<NB, NSTATE>>>(out);
    sub_kernel<<<M_TOT, 256>>>(out);
}

// round 4
// speedup vs baseline: 1.6519x; 1.6519x over previous
#include <cuda_runtime.h>
#include <cuda_bf16.h>
#include <cstdint>
#include <cstddef>

// Problem constants
#define T_LEN 800
#define NB    32
#define LIN   4000
#define FEATC 320
#define KW    19
#define PADL  7
#define NSTATE 1024
#define NZ    5
#define CN    5120           // NSTATE * NZ
#define M_TOT (T_LEN * NB)   // 25600
#define KTOT  960            // 3 * FEATC (hi|lo|hi split)

// GEMM tiling
#define BM 128
#define BN 256
#define BK 32
#define NKT (KTOT / BK)      // 30
#define STAGES 4
#define A_STAGE 8192         // 128 rows * 64 B
#define B_STAGE 16384        // 256 rows * 64 B
#define SMEM_TOTAL (STAGES * (A_STAGE + B_STAGE))   // 98304

// Scratch (no allocations allowed)
__device__ __nv_bfloat16 g_A[M_TOT * KTOT];   // [M, 960] = tanh: hi | lo | hi
__device__ __nv_bfloat16 g_B[CN * KTOT];      // [N, 960] = w:    hi | hi | lo
__device__ float g_logz_over_T[NB];

// ---------------------------------------------------------------------------
// helpers
// ---------------------------------------------------------------------------
__device__ __forceinline__ uint32_t smem_u32(const void* p) {
    uint32_t a;
    asm("{ .reg .u64 t; cvta.to.shared.u64 t, %1; cvt.u32.u64 %0, t; }"
        : "=r"(a) : "l"(p));
    return a;
}
__device__ __forceinline__ float fast_tanh(float x) {
    float r;
    asm("tanh.approx.f32 %0, %1;" : "=f"(r) : "f"(x));
    return r;
}
#define CP_ASYNC16(saddr, gptr)                                                \
    asm volatile("cp.async.cg.shared.global [%0], [%1], 16;"                   \
                 :: "r"(saddr), "l"(gptr) : "memory")
#define CP_COMMIT() asm volatile("cp.async.commit_group;" ::: "memory")
#define CP_WAIT(n)  asm volatile("cp.async.wait_group %0;" :: "n"(n) : "memory")

#define LDMATRIX_X4(r, addr)                                                   \
    asm volatile("ldmatrix.sync.aligned.m8n8.x4.shared.b16 {%0,%1,%2,%3}, [%4];" \
                 : "=r"((r)[0]), "=r"((r)[1]), "=r"((r)[2]), "=r"((r)[3])      \
                 : "r"(addr))

#define MMA16816(d, a, b0, b1)                                                 \
    asm volatile("mma.sync.aligned.m16n8k16.row.col.f32.bf16.bf16.f32 "        \
                 "{%0,%1,%2,%3}, {%4,%5,%6,%7}, {%8,%9}, {%0,%1,%2,%3};"       \
                 : "+f"((d)[0]), "+f"((d)[1]), "+f"((d)[2]), "+f"((d)[3])      \
                 : "r"((a)[0]), "r"((a)[1]), "r"((a)[2]), "r"((a)[3]),         \
                   "r"(b0), "r"(b1))

// ---------------------------------------------------------------------------
// Kernel 1: strided conv + tanh -> g_A rows (hi | lo | hi)
// ---------------------------------------------------------------------------
#define TCHUNK 16
#define XSEG ((TCHUNK - 1) * 5 + KW)   // 94

__global__ void conv_kernel(const float* __restrict__ x,
                            const float* __restrict__ w,
                            const float* __restrict__ b) {
    __shared__ float sw[FEATC * KW];
    __shared__ float sb[FEATC];
    __shared__ float sx[XSEG];

    const int n  = blockIdx.y;
    const int t0 = blockIdx.x * TCHUNK;
    const int tid = threadIdx.x;

    for (int i = tid; i < FEATC * KW; i += blockDim.x) sw[i] = w[i];
    if (tid < FEATC) sb[tid] = b[tid];
    const int base = t0 * 5 - PADL;
    for (int i = tid; i < XSEG; i += blockDim.x) {
        int gx = base + i;
        sx[i] = (gx >= 0 && gx < LIN) ? x[n * LIN + gx] : 0.0f;
    }
    __syncthreads();

    const int f = tid;
    float acc[TCHUNK];
#pragma unroll
    for (int i = 0; i < TCHUNK; i++) acc[i] = sb[f];
#pragma unroll
    for (int k = 0; k < KW; k++) {
        const float wk = sw[f * KW + k];
#pragma unroll
        for (int i = 0; i < TCHUNK; i++) acc[i] += wk * sx[i * 5 + k];
    }
#pragma unroll
    for (int i = 0; i < TCHUNK; i++) {
        const int row = (t0 + i) * NB + n;
        float v = fast_tanh(acc[i]);
        __nv_bfloat16 hi = __float2bfloat16(v);
        __nv_bfloat16 lo = __float2bfloat16(v - __bfloat162float(hi));
        __nv_bfloat16* dst = g_A + (size_t)row * KTOT;
        dst[f] = hi;
        dst[FEATC + f] = lo;
        dst[2 * FEATC + f] = hi;
    }
}

// ---------------------------------------------------------------------------
// Kernel 1b: transpose+split lin_w [320,5120] -> g_B [5120, 960] (hi|hi|lo)
// ---------------------------------------------------------------------------
__global__ void convb_kernel(const float* __restrict__ w) {
    int i = blockIdx.x * blockDim.x + threadIdx.x;   // over 320*5120
    if (i >= FEATC * CN) return;
    int f = i / CN;
    int c = i % CN;
    float v = w[i];
    __nv_bfloat16 hi = __float2bfloat16(v);
    __nv_bfloat16 lo = __float2bfloat16(v - __bfloat162float(hi));
    __nv_bfloat16* dst = g_B + (size_t)c * KTOT;
    dst[f] = hi;
    dst[FEATC + f] = hi;
    dst[2 * FEATC + f] = lo;
}

// ---------------------------------------------------------------------------
// Kernel 2: HMMA bf16 GEMM. out[m,c] = 5*tanh(sum + bias[c]).
// Block 128x256, 8 warps (2x4), warp tile 64x64, BK=32, 4-stage cp.async.
// Smem rows are 64B (32 bf16) with 16B-chunk XOR swizzle: chunk ^= (row>>1)&3.
// ---------------------------------------------------------------------------
__global__ __launch_bounds__(256, 1)
void hmma_gemm_kernel(const float* __restrict__ lin_b,
                      float* __restrict__ out) {
    extern __shared__ __align__(1024) char smem[];
    const uint32_t sbase = smem_u32(smem);
    const uint32_t sA = sbase;
    const uint32_t sB = sbase + STAGES * A_STAGE;

    const int tid  = threadIdx.x;
    const int wid  = tid >> 5;
    const int lane = tid & 31;
    const int g = lane >> 2;       // group (row/col within frag)
    const int t = lane & 3;
    const int warp_m = (wid & 1) * 64;
    const int warp_n = (wid >> 1) * 64;
    const int bn = blockIdx.x;     // 0..19
    const int bm = blockIdx.y;     // 0..199

    const __nv_bfloat16* gA = g_A + (size_t)bm * BM * KTOT;
    const __nv_bfloat16* gB = g_B + (size_t)bn * BN * KTOT;

    // ---- stage loader (cp.async, 16B granules) ----
#define LOAD_STAGE(stg, kt)                                                    \
    do {                                                                       \
        _Pragma("unroll")                                                      \
        for (int i = 0; i < 2; i++) {                                          \
            int idx = tid + i * 256;                                           \
            int row = idx >> 2, ch = idx & 3;                                  \
            const __nv_bfloat16* gp = gA + (size_t)row * KTOT + (kt) * BK + ch * 8; \
            uint32_t sp = sA + (stg) * A_STAGE + row * 64 +                    \
                          ((ch ^ ((row >> 1) & 3)) << 4);                      \
            CP_ASYNC16(sp, gp);                                                \
        }                                                                      \
        _Pragma("unroll")                                                      \
        for (int i = 0; i < 4; i++) {                                          \
            int idx = tid + i * 256;                                           \
            int row = idx >> 2, ch = idx & 3;                                  \
            const __nv_bfloat16* gp = gB + (size_t)row * KTOT + (kt) * BK + ch * 8; \
            uint32_t sp = sB + (stg) * B_STAGE + row * 64 +                    \
                          ((ch ^ ((row >> 1) & 3)) << 4);                      \
            CP_ASYNC16(sp, gp);                                                \
        }                                                                      \
    } while (0)

    float acc[4][8][4];
#pragma unroll
    for (int mi = 0; mi < 4; mi++)
#pragma unroll
        for (int ni = 0; ni < 8; ni++)
#pragma unroll
            for (int r = 0; r < 4; r++) acc[mi][ni][r] = 0.0f;

    // prologue: fill STAGES-1 stages
#pragma unroll
    for (int s = 0; s < STAGES - 1; s++) {
        LOAD_STAGE(s, s);
        CP_COMMIT();
    }

    for (int kt = 0; kt < NKT; kt++) {
        CP_WAIT(STAGES - 2);
        __syncthreads();

        const int nk = kt + STAGES - 1;
        if (nk < NKT) LOAD_STAGE(nk % STAGES, nk);
        CP_COMMIT();

        const uint32_t aBase = sA + (kt % STAGES) * A_STAGE;
        const uint32_t bBase = sB + (kt % STAGES) * B_STAGE;
        const int aoff = (kt % STAGES) * A_STAGE + STAGES * A_STAGE; // unused marker
        (void)aoff;

#pragma unroll
        for (int ks = 0; ks < 2; ks++) {
            // A fragments via ldmatrix.x4
            uint32_t af[4][4];
#pragma unroll
            for (int mi = 0; mi < 4; mi++) {
                int m = warp_m + mi * 16 + ((lane >> 3) & 1) * 8 + (lane & 7);
                int chL = ks * 2 + (lane >> 4);
                uint32_t addr = aBase + m * 64 + ((chL ^ ((m >> 1) & 3)) << 4);
                LDMATRIX_X4(af[mi], addr);
            }
            // B fragments via direct LDS.32 from [n][k] rows
            const char* bptr = smem + (bBase - sbase);
#pragma unroll
            for (int ni = 0; ni < 8; ni++) {
                int n = warp_n + ni * 8 + g;
                int swz = (n >> 1) & 3;
                uint32_t b0 = *(const uint32_t*)(bptr + n * 64 +
                                (((ks * 2) ^ swz) << 4) + t * 4);
                uint32_t b1 = *(const uint32_t*)(bptr + n * 64 +
                                (((ks * 2 + 1) ^ swz) << 4) + t * 4);
#pragma unroll
                for (int mi = 0; mi < 4; mi++)
                    MMA16816(acc[mi][ni], af[mi], b0, b1);
            }
        }
    }

    // ---- epilogue: bias + 5*tanh + store ----
#pragma unroll
    for (int mi = 0; mi < 4; mi++) {
        const int row0 = bm * BM + warp_m + mi * 16 + g;
#pragma unroll
        for (int ni = 0; ni < 8; ni++) {
            const int col = bn * BN + warp_n + ni * 8 + 2 * t;
            const float2 bb = *(const float2*)(lin_b + col);
            float v0 = 5.0f * fast_tanh(acc[mi][ni][0] + bb.x);
            float v1 = 5.0f * fast_tanh(acc[mi][ni][1] + bb.y);
            float v2 = 5.0f * fast_tanh(acc[mi][ni][2] + bb.x);
            float v3 = 5.0f * fast_tanh(acc[mi][ni][3] + bb.y);
            *(float2*)(out + (size_t)row0 * CN + col) = make_float2(v0, v1);
            *(float2*)(out + (size_t)(row0 + 8) * CN + col) = make_float2(v2, v3);
        }
    }
}

// ---------------------------------------------------------------------------
// Kernel 3: log-semiring forward scan. One block per batch element.
// ---------------------------------------------------------------------------
__global__ __launch_bounds__(1024, 1)
void scan_kernel(const float* __restrict__ scores) {
    __shared__ float alpha[2][NSTATE];
    __shared__ float rmax[32];
    __shared__ float rsum[32];
    __shared__ float sfinal;

    const int n = blockIdx.x;
    const int c = threadIdx.x;
    const int q = c >> 2;

    alpha[0][c] = 0.0f;
    __syncthreads();

    const float* p = scores + (size_t)n * CN + (size_t)c * NZ;
    const size_t tstride = (size_t)NB * CN;

    float m0 = p[0], m1 = p[1], m2 = p[2], m3 = p[3], m4 = p[4];
    int cur = 0;
    for (int t = 0; t < T_LEN; t++) {
        float n0 = 0.f, n1 = 0.f, n2 = 0.f, n3 = 0.f, n4 = 0.f;
        if (t + 1 < T_LEN) {
            const float* pn = p + (size_t)(t + 1) * tstride;
            n0 = pn[0]; n1 = pn[1]; n2 = pn[2]; n3 = pn[3]; n4 = pn[4];
        }
        const float s0 = m0 + alpha[cur][c];
        const float s1 = m1 + alpha[cur][q];
        const float s2 = m2 + alpha[cur][q + 256];
        const float s3 = m3 + alpha[cur][q + 512];
        const float s4 = m4 + alpha[cur][q + 768];
        float mx = fmaxf(fmaxf(fmaxf(s0, s1), fmaxf(s2, s3)), s4);
        float sum = __expf(s0 - mx) + __expf(s1 - mx) + __expf(s2 - mx) +
                    __expf(s3 - mx) + __expf(s4 - mx);
        alpha[cur ^ 1][c] = mx + __logf(sum);
        __syncthreads();
        cur ^= 1;
        m0 = n0; m1 = n1; m2 = n2; m3 = n3; m4 = n4;
    }

    const float v = alpha[cur][c];
    float mx = v;
#pragma unroll
    for (int o = 16; o > 0; o >>= 1)
        mx = fmaxf(mx, __shfl_xor_sync(0xffffffffu, mx, o));
    if ((c & 31) == 0) rmax[c >> 5] = mx;
    __syncthreads();
    if (c < 32) {
        float m2r = rmax[c];
#pragma unroll
        for (int o = 16; o > 0; o >>= 1)
            m2r = fmaxf(m2r, __shfl_xor_sync(0xffffffffu, m2r, o));
        if (c == 0) sfinal = m2r;
    }
    __syncthreads();
    float e = __expf(v - sfinal);
#pragma unroll
    for (int o = 16; o > 0; o >>= 1)
        e += __shfl_xor_sync(0xffffffffu, e, o);
    if ((c & 31) == 0) rsum[c >> 5] = e;
    __syncthreads();
    if (c < 32) {
        float s = rsum[c];
#pragma unroll
        for (int o = 16; o > 0; o >>= 1)
            s += __shfl_xor_sync(0xffffffffu, s, o);
        if (c == 0)
            g_logz_over_T[n] = (sfinal + logf(s)) * (1.0f / (float)T_LEN);
    }
}

// ---------------------------------------------------------------------------
// Kernel 4: in-place global-norm subtraction
// ---------------------------------------------------------------------------
__global__ void sub_kernel(float* __restrict__ out) {
    const int row = blockIdx.x;             // t*NB + n
    const float s = g_logz_over_T[row & (NB - 1)];
    float4* p = (float4*)(out + (size_t)row * CN);
#pragma unroll
    for (int j = threadIdx.x; j < CN / 4; j += 256) {
        float4 v = p[j];
        v.x -= s; v.y -= s; v.z -= s; v.w -= s;
        p[j] = v;
    }
}

// ---------------------------------------------------------------------------
extern "C" void kernel_launch(void* const* d_in, const int* in_sizes, int n_in,
                              void* d_out, int out_size) {
    const float* x      = (const float*)d_in[0];
    const float* conv_w = (const float*)d_in[1];
    const float* conv_b = (const float*)d_in[2];
    const float* lin_w  = (const float*)d_in[3];
    const float* lin_b  = (const float*)d_in[4];
    float* out = (float*)d_out;

    static bool attr_set = false;
    if (!attr_set) {
        cudaFuncSetAttribute(hmma_gemm_kernel,
                             cudaFuncAttributeMaxDynamicSharedMemorySize,
                             SMEM_TOTAL);
        attr_set = true;
    }

    conv_kernel<<<dim3(T_LEN / TCHUNK, NB), FEATC>>>(x, conv_w, conv_b);
    convb_kernel<<<(FEATC * CN + 255) / 256, 256>>>(lin_w);
    hmma_gemm_kernel<<<dim3(CN / BN, M_TOT / BM), 256, SMEM_TOTAL>>>(lin_b, out);
    scan_kernel<<<NB, NSTATE>>>(out);
    sub_kernel<<<M_TOT, 256>>>(out);
}